// round 5
// baseline (speedup 1.0000x reference)
#include <cuda_runtime.h>
#include <cuda_bf16.h>
#include <cstdint>

// Problem constants (fixed shapes)
#define NN 4096
#define FF 128
#define HEADS 8
#define UU 8
#define NCOL 160        // 80 hi cols + 80 lo cols
#define MT 128          // GEMM M-tile
#define KSPLIT 4        // K-splits
#define KPC 1024        // K per CTA
#define KC 32           // K chunk per pipeline stage
#define NCHUNK (KPC / KC)   // 32
#define SSTR 40         // smem K-stride (elements)

// ---------------- device scratch (no allocations allowed) ----------------
__device__ __nv_bfloat16 g_Xp[NCOL * NN];           // [col][node]
__device__ float g_el[HEADS * NN];                  // e_left per head/node
__device__ float g_part[KSPLIT][NN][NCOL];          // GEMM partials (10.5 MB)

// ---------------- prep kernel: build Xp and e_l ----------------
// block 256 threads = 32 nodes x 8 heads; grid 128
__global__ __launch_bounds__(256) void gat_build(
    const float* __restrict__ H, const float* __restrict__ W,
    const float* __restrict__ al, const float* __restrict__ ar)
{
    __shared__ float sW[FF * 64];     // [f*64 + h*8 + u] = 32 KB
    __shared__ float sal[64], sar[64];

    const int tid = threadIdx.x;
    for (int i = tid; i < HEADS * FF * UU; i += 256) {
        int h = i >> 10, rem = i & 1023;
        int f = rem >> 3, u = rem & 7;
        sW[f * 64 + h * 8 + u] = W[i];
    }
    if (tid < 64) { sal[tid] = al[tid]; sar[tid] = ar[tid]; }
    __syncthreads();

    const int h = tid & 7;
    const int n = blockIdx.x * 32 + (tid >> 3);

    float hw[8];
#pragma unroll
    for (int u = 0; u < 8; u++) hw[u] = 0.f;

    const float4* H4 = reinterpret_cast<const float4*>(H + (size_t)n * FF);

#pragma unroll 4
    for (int fq = 0; fq < FF / 4; fq++) {
        float4 x = __ldg(H4 + fq);
        const float xe[4] = {x.x, x.y, x.z, x.w};
#pragma unroll
        for (int e = 0; e < 4; e++) {
            int f = fq * 4 + e;
            float4 w0 = *reinterpret_cast<const float4*>(sW + f * 64 + h * 8);
            float4 w1 = *reinterpret_cast<const float4*>(sW + f * 64 + h * 8 + 4);
            float a = xe[e];
            hw[0] += a * w0.x; hw[1] += a * w0.y; hw[2] += a * w0.z; hw[3] += a * w0.w;
            hw[4] += a * w1.x; hw[5] += a * w1.y; hw[6] += a * w1.z; hw[7] += a * w1.w;
        }
    }

    float el = 0.f, er = 0.f;
#pragma unroll
    for (int u = 0; u < 8; u++) {
        el += hw[u] * sal[h * 8 + u];
        er += hw[u] * sar[h * 8 + u];
    }
    const float s = expf(er);
    g_el[h * NN + n] = el;

#pragma unroll
    for (int u = 0; u < 8; u++) {
        float v = s * hw[u];
        __nv_bfloat16 hi = __float2bfloat16(v);
        float lo = v - __bfloat162float(hi);
        g_Xp[(h * 8 + u) * NN + n] = hi;
        g_Xp[(80 + h * 8 + u) * NN + n] = __float2bfloat16(lo);
    }
    {
        __nv_bfloat16 shi = __float2bfloat16(s);
        float slo = s - __bfloat162float(shi);
        g_Xp[(64 + h) * NN + n] = shi;
        g_Xp[(144 + h) * NN + n] = __float2bfloat16(slo);
    }
    if (h == 0) {
        const __nv_bfloat16 one = __float2bfloat16(1.0f);
        const __nv_bfloat16 zero = __float2bfloat16(0.0f);
        g_Xp[72 * NN + n] = one;
        g_Xp[152 * NN + n] = zero;
#pragma unroll
        for (int c2 = 73; c2 < 80; c2++) {
            g_Xp[c2 * NN + n] = zero;
            g_Xp[(c2 + 80) * NN + n] = zero;
        }
    }
}

// ---------------- bf16 mma helper ----------------
__device__ __forceinline__ void mma16816v(float c[4], const uint32_t a0, const uint32_t a1,
                                          const uint32_t a2, const uint32_t a3,
                                          uint32_t b0, uint32_t b1)
{
    asm volatile(
        "mma.sync.aligned.m16n8k16.row.col.f32.bf16.bf16.f32 "
        "{%0,%1,%2,%3}, {%4,%5,%6,%7}, {%8,%9}, {%0,%1,%2,%3};\n"
        : "+f"(c[0]), "+f"(c[1]), "+f"(c[2]), "+f"(c[3])
        : "r"(a0), "r"(a1), "r"(a2), "r"(a3), "r"(b0), "r"(b1));
}

// ---------------- GEMM: A[4096x4096] @ Xp[4096x160], K-split partials ----------------
// grid (32, 4): x = M-tile, y = K-split. 512 threads = 16 warps (4 M x 4 N).
__global__ __launch_bounds__(512, 1) void gat_gemm(const float* __restrict__ A)
{
    __shared__ __align__(16) __nv_bfloat16 As[2][MT * SSTR];    // 2 x 10 KB
    __shared__ __align__(16) __nv_bfloat16 Bs[2][NCOL * SSTR];  // 2 x 12.5 KB

    const int tid = threadIdx.x;
    const int lane = tid & 31, wid = tid >> 5;
    const int g = lane >> 2, tg = lane & 3;
    const int wm = wid & 3;        // 0..3  (rows 32*wm)
    const int wn = wid >> 2;       // 0..3  (cols 40*wn)
    const int rowBase = blockIdx.x * MT;
    const int kBase0 = blockIdx.y * KPC;

    // A loader: 4 threads cover one 32-float row-chunk (KC=32)
    const int arow = tid >> 2;            // 0..127
    const int acol = (tid & 3) * 8;       // 0,8,16,24
    const float* Aptr = A + (size_t)(rowBase + arow) * NN + kBase0 + acol;

    // B loader: 5 uint32 per thread (2560 total per stage)
    float4 pa0[2], pa1[2];
    uint32_t pb[5];

#pragma unroll
    for (int j = 0; j < 2; j++) pa0[j] = *reinterpret_cast<const float4*>(Aptr + j * 4);
#pragma unroll
    for (int j = 0; j < 2; j++) pa1[j] = *reinterpret_cast<const float4*>(Aptr + KC + j * 4);
#pragma unroll
    for (int it = 0; it < 5; it++) {
        int idx = tid + it * 512;
        int cc = idx >> 4, kp = (idx & 15) * 2;
        pb[it] = *reinterpret_cast<const uint32_t*>(g_Xp + cc * NN + kBase0 + kp);
    }

    float acc[2][5][4];
#pragma unroll
    for (int mt = 0; mt < 2; mt++)
#pragma unroll
        for (int nt = 0; nt < 5; nt++)
#pragma unroll
            for (int q = 0; q < 4; q++) acc[mt][nt][q] = 0.f;

#pragma unroll 1
    for (int c = 0; c < NCHUNK; c++) {
        const int buf = c & 1;
        float4* pa = (buf == 0) ? pa0 : pa1;
        __nv_bfloat16* as = As[buf];
        __nv_bfloat16* bs = Bs[buf];

        // ---- STS A (fp32 regs -> bf16 smem) ----
#pragma unroll
        for (int j = 0; j < 2; j++) {
            __nv_bfloat162 p0 = __floats2bfloat162_rn(pa[j].x, pa[j].y);
            __nv_bfloat162 p1 = __floats2bfloat162_rn(pa[j].z, pa[j].w);
            uint2 v;
            v.x = *reinterpret_cast<uint32_t*>(&p0);
            v.y = *reinterpret_cast<uint32_t*>(&p1);
            *reinterpret_cast<uint2*>(as + arow * SSTR + acol + j * 4) = v;
        }
        // ---- STS B ----
#pragma unroll
        for (int it = 0; it < 5; it++) {
            int idx = tid + it * 512;
            int cc = idx >> 4, kp = (idx & 15) * 2;
            *reinterpret_cast<uint32_t*>(bs + cc * SSTR + kp) = pb[it];
        }
        // ---- prefetch: A 2 ahead, B 1 ahead ----
        if (c + 2 < NCHUNK) {
#pragma unroll
            for (int j = 0; j < 2; j++)
                pa[j] = *reinterpret_cast<const float4*>(Aptr + (c + 2) * KC + j * 4);
        }
        if (c + 1 < NCHUNK) {
#pragma unroll
            for (int it = 0; it < 5; it++) {
                int idx = tid + it * 512;
                int cc = idx >> 4, kp = (idx & 15) * 2;
                pb[it] = *reinterpret_cast<const uint32_t*>(
                    g_Xp + cc * NN + kBase0 + (c + 1) * KC + kp);
            }
        }
        __syncthreads();

        // ---- MMA over staged chunk (2 x k16) ----
#pragma unroll
        for (int k16 = 0; k16 < 2; k16++) {
            const int kb = k16 * 16;
            uint32_t a[2][4];
#pragma unroll
            for (int mt = 0; mt < 2; mt++) {
                int r = wm * 32 + mt * 16 + g;
                a[mt][0] = *reinterpret_cast<const uint32_t*>(as + r * SSTR + kb + tg * 2);
                a[mt][1] = *reinterpret_cast<const uint32_t*>(as + (r + 8) * SSTR + kb + tg * 2);
                a[mt][2] = *reinterpret_cast<const uint32_t*>(as + r * SSTR + kb + 8 + tg * 2);
                a[mt][3] = *reinterpret_cast<const uint32_t*>(as + (r + 8) * SSTR + kb + 8 + tg * 2);
            }
#pragma unroll
            for (int nt = 0; nt < 5; nt++) {
                int col = wn * 40 + nt * 8 + g;
                uint32_t b0 = *reinterpret_cast<const uint32_t*>(bs + col * SSTR + kb + tg * 2);
                uint32_t b1 = *reinterpret_cast<const uint32_t*>(bs + col * SSTR + kb + 8 + tg * 2);
#pragma unroll
                for (int mt = 0; mt < 2; mt++)
                    mma16816v(acc[mt][nt], a[mt][0], a[mt][1], a[mt][2], a[mt][3], b0, b1);
            }
        }
    }

    // ---- store partials to scratch ----
    float* pp = &g_part[blockIdx.y][0][0];
#pragma unroll
    for (int mt = 0; mt < 2; mt++) {
#pragma unroll
        for (int nt = 0; nt < 5; nt++) {
            int r = rowBase + wm * 32 + mt * 16 + g;
            int col = wn * 40 + nt * 8 + tg * 2;
            float2 v0 = make_float2(acc[mt][nt][0], acc[mt][nt][1]);
            float2 v1 = make_float2(acc[mt][nt][2], acc[mt][nt][3]);
            *reinterpret_cast<float2*>(pp + (size_t)r * NCOL + col) = v0;
            *reinterpret_cast<float2*>(pp + (size_t)(r + 8) * NCOL + col) = v1;
        }
    }
}

// ---------------- epilogue: reduce K-splits + softmax-normalize + elu ----------------
__global__ __launch_bounds__(256) void gat_epilogue(float* __restrict__ out)
{
    const int t = blockIdx.x * 256 + threadIdx.x;
    const int n = t >> 3, h = t & 7;

    float4 hi0 = make_float4(0, 0, 0, 0), hi1 = hi0, lo0 = hi0, lo1 = hi0;
    float sden = 0.f, deg = 0.f;
#pragma unroll
    for (int s = 0; s < KSPLIT; s++) {
        const float* base = &g_part[s][n][0];
        float4 a0 = *reinterpret_cast<const float4*>(base + h * 8);
        float4 a1 = *reinterpret_cast<const float4*>(base + h * 8 + 4);
        float4 b0 = *reinterpret_cast<const float4*>(base + 80 + h * 8);
        float4 b1 = *reinterpret_cast<const float4*>(base + 80 + h * 8 + 4);
        hi0.x += a0.x; hi0.y += a0.y; hi0.z += a0.z; hi0.w += a0.w;
        hi1.x += a1.x; hi1.y += a1.y; hi1.z += a1.z; hi1.w += a1.w;
        lo0.x += b0.x; lo0.y += b0.y; lo0.z += b0.z; lo0.w += b0.w;
        lo1.x += b1.x; lo1.y += b1.y; lo1.z += b1.z; lo1.w += b1.w;
        sden += base[64 + h] + base[144 + h];
        deg  += base[72] + base[152];
    }

    const float e = expf(g_el[h * NN + n]);
    const float denom = (float)NN - deg + e * sden;
    const float r = e / denom;

    float v[8];
    v[0] = (hi0.x + lo0.x) * r; v[1] = (hi0.y + lo0.y) * r;
    v[2] = (hi0.z + lo0.z) * r; v[3] = (hi0.w + lo0.w) * r;
    v[4] = (hi1.x + lo1.x) * r; v[5] = (hi1.y + lo1.y) * r;
    v[6] = (hi1.z + lo1.z) * r; v[7] = (hi1.w + lo1.w) * r;

    float4 o0, o1;
    o0.x = v[0] > 0.f ? v[0] : expm1f(v[0]);
    o0.y = v[1] > 0.f ? v[1] : expm1f(v[1]);
    o0.z = v[2] > 0.f ? v[2] : expm1f(v[2]);
    o0.w = v[3] > 0.f ? v[3] : expm1f(v[3]);
    o1.x = v[4] > 0.f ? v[4] : expm1f(v[4]);
    o1.y = v[5] > 0.f ? v[5] : expm1f(v[5]);
    o1.z = v[6] > 0.f ? v[6] : expm1f(v[6]);
    o1.w = v[7] > 0.f ? v[7] : expm1f(v[7]);

    float4* op = reinterpret_cast<float4*>(out + (size_t)n * (HEADS * UU) + h * 8);
    op[0] = o0;
    op[1] = o1;
}

// ---------------- launcher ----------------
extern "C" void kernel_launch(void* const* d_in, const int* in_sizes, int n_in,
                              void* d_out, int out_size)
{
    (void)in_sizes; (void)n_in; (void)out_size;
    const float* A  = (const float*)d_in[0];
    const float* H  = (const float*)d_in[1];
    const float* W  = (const float*)d_in[2];
    const float* al = (const float*)d_in[3];
    const float* ar = (const float*)d_in[4];
    float* out = (float*)d_out;

    gat_build<<<NN / 32, 256>>>(H, W, al, ar);
    dim3 gg(NN / MT, KSPLIT);
    gat_gemm<<<gg, 512>>>(A);
    gat_epilogue<<<NN * HEADS / 256, 256>>>(out);
}